// round 14
// baseline (speedup 1.0000x reference)
#include <cuda_runtime.h>
#include <cuda_fp16.h>
#include <cstdint>
#include <math.h>

#define D_MODEL 1024
#define N_HEADS 16
#define HDIM    64
#define SEQ     2048
#define BATCH   2
#define ROWS    (BATCH * SEQ)   // 4096

// ---------------------------------------------------------------------------
// Scratch (static device globals — no allocation allowed)
// ---------------------------------------------------------------------------
__device__ float2 g_angtab[SEQ * 32];                         // (cos, sin)
__device__ __half g_qh[ROWS * D_MODEL];                       // Q hi (roped)
__device__ __half g_kh[ROWS * D_MODEL];                       // K hi (roped)
__device__ __half g_vth[BATCH * N_HEADS * HDIM * SEQ];        // V^T hi [bh*64+d][s]
__device__ __half g_xh[ROWS * D_MODEL];                       // X hi
__device__ __half g_ath[ROWS * D_MODEL];                      // att hi
__device__ __half g_wqh[D_MODEL * D_MODEL];
__device__ __half g_wqm[D_MODEL * D_MODEL];
__device__ __half g_wkh[D_MODEL * D_MODEL];
__device__ __half g_wkm[D_MODEL * D_MODEL];
__device__ __half g_wvh[D_MODEL * D_MODEL];
__device__ __half g_wvm[D_MODEL * D_MODEL];
__device__ __half g_woh[D_MODEL * D_MODEL];
__device__ __half g_wom[D_MODEL * D_MODEL];

// ---------------------------------------------------------------------------
// Helpers
// ---------------------------------------------------------------------------
__device__ __forceinline__ uint32_t smem_u32(const void* p) {
    uint32_t a;
    asm("{ .reg .u64 t; cvta.to.shared.u64 t, %1; cvt.u32.u64 %0, t; }"
        : "=r"(a) : "l"(p));
    return a;
}
__device__ __forceinline__ void cp_async16(uint32_t saddr, const void* gptr) {
    asm volatile("cp.async.cg.shared.global [%0], [%1], 16;"
                 :: "r"(saddr), "l"(gptr) : "memory");
}
__device__ __forceinline__ void cp_commit() {
    asm volatile("cp.async.commit_group;" ::: "memory");
}
template <int N>
__device__ __forceinline__ void cp_wait() {
    asm volatile("cp.async.wait_group %0;" :: "n"(N) : "memory");
}
__device__ __forceinline__ void mma_f16(float* d, const uint32_t* a,
                                        const uint32_t* b) {
    asm volatile(
        "mma.sync.aligned.m16n8k16.row.col.f32.f16.f16.f32 "
        "{%0,%1,%2,%3}, {%4,%5,%6,%7}, {%8,%9}, {%0,%1,%2,%3};"
        : "+f"(d[0]), "+f"(d[1]), "+f"(d[2]), "+f"(d[3])
        : "r"(a[0]), "r"(a[1]), "r"(a[2]), "r"(a[3]), "r"(b[0]), "r"(b[1]));
}
__device__ __forceinline__ void ldsm4(uint32_t* r, uint32_t addr) {
    asm volatile("ldmatrix.sync.aligned.m8n8.x4.shared.b16 {%0,%1,%2,%3}, [%4];"
                 : "=r"(r[0]), "=r"(r[1]), "=r"(r[2]), "=r"(r[3]) : "r"(addr));
}
__device__ __forceinline__ uint32_t pack_f16(float lo, float hi) {
    uint32_t r;
    asm("cvt.rn.f16x2.f32 %0, %1, %2;" : "=r"(r) : "f"(hi), "f"(lo));
    return r;
}

// FFMA-only exp, accurate ~1e-7 on [-87, 0]
__device__ __forceinline__ float fast_exp(float x) {
    x = fmaxf(x, -87.0f);
    float y = x * 1.4426950408889634f;
    float r = y + 12582912.0f;
    float n = r - 12582912.0f;
    float f = y - n;
    float t = f * 0.6931471805599453f;
    float p = 1.3888889e-3f;
    p = fmaf(p, t, 8.3333333e-3f);
    p = fmaf(p, t, 4.1666667e-2f);
    p = fmaf(p, t, 1.6666667e-1f);
    p = fmaf(p, t, 0.5f);
    p = fmaf(p, t, 1.0f);
    p = fmaf(p, t, 1.0f);
    int ni = __float_as_int(r) - 0x4B400000;
    float scale = __int_as_float((ni << 23) + 0x3F800000);
    return p * scale;
}

// ---------------------------------------------------------------------------
// RoPE angle table
// ---------------------------------------------------------------------------
__global__ __launch_bounds__(256)
void angtab_kernel(float2* __restrict__ tab)
{
    int idx = blockIdx.x * blockDim.x + threadIdx.x;
    int t = idx >> 5;
    int i = idx & 31;
    float inv = 1.0f / powf(10000.0f, (float)(2 * i) * (1.0f / 64.0f));
    float ang = (float)t * inv;
    float sn, cs;
    sincosf(ang, &sn, &cs);
    tab[idx] = make_float2(cs, sn);
}

// ---------------------------------------------------------------------------
// Weight split (hi + mid), fused over the 4 matrices.
// ---------------------------------------------------------------------------
#define W_UNITS (D_MODEL * D_MODEL / 4)

__global__ __launch_bounds__(256)
void split_w4_kernel(const float* __restrict__ w0, const float* __restrict__ w1,
                     const float* __restrict__ w2, const float* __restrict__ w3,
                     __half* __restrict__ h0, __half* __restrict__ m0,
                     __half* __restrict__ h1, __half* __restrict__ m1,
                     __half* __restrict__ h2, __half* __restrict__ m2,
                     __half* __restrict__ h3, __half* __restrict__ m3)
{
    int idx = blockIdx.x * blockDim.x + threadIdx.x;
    int u   = idx * 2;
    int mat = u >> 18;
    int rem = u & (W_UNITS - 1);
    const float* src; __half *hh, *mm;
    if (mat == 0)      { src = w0; hh = h0; mm = m0; }
    else if (mat == 1) { src = w1; hh = h1; mm = m1; }
    else if (mat == 2) { src = w2; hh = h2; mm = m2; }
    else               { src = w3; hh = h3; mm = m3; }
#pragma unroll
    for (int j = 0; j < 2; j++) {
        int o = rem + j;
        float4 x = *(const float4*)(src + o * 4);
        __half ha = __float2half_rn(x.x);
        __half hb = __float2half_rn(x.y);
        __half hc = __float2half_rn(x.z);
        __half hd = __float2half_rn(x.w);
        __half2* hp = (__half2*)(hh + o * 4);
        hp[0] = __half2(ha, hb);
        hp[1] = __half2(hc, hd);
        __half2* mp = (__half2*)(mm + o * 4);
        mp[0] = __half2(__float2half_rn(x.x - __half2float(ha)),
                        __float2half_rn(x.y - __half2float(hb)));
        mp[1] = __half2(__float2half_rn(x.z - __half2float(hc)),
                        __float2half_rn(x.w - __half2float(hd)));
    }
}

// X split (hi only)
__global__ __launch_bounds__(256)
void split1_kernel(const float* __restrict__ src, __half* __restrict__ h, int n4)
{
    int idx = blockIdx.x * blockDim.x + threadIdx.x;
#pragma unroll
    for (int j = 0; j < 2; j++) {
        int o = idx * 2 + j;
        if (o >= n4) return;
        float4 x = *(const float4*)(src + o * 4);
        __half2* hp = (__half2*)(h + o * 4);
        hp[0] = __half2(__float2half_rn(x.x), __float2half_rn(x.y));
        hp[1] = __half2(__float2half_rn(x.z), __float2half_rn(x.w));
    }
}

// ---------------------------------------------------------------------------
// fp16x2 GEMM: 128-thread CTA (4 warps as 2x2), CTA tile 128x64 (one head),
// warp tile 64x32. 3-stage cp.async ring, XOR swizzle, ldmatrix.
// MODE 0: C += bias (fp32 out).  MODE 1: rope -> fp16 H.  MODE 2: V^T fp16 H.
// ---------------------------------------------------------------------------
#define BK2      32
#define NCH2     (D_MODEL / BK2)       // 32 chunks
#define BUF_W    4096                  // words per stage (16KB)
#define A_OFF_W  0
#define WH_OFF_W 2048
#define WM_OFF_W 3072
#define GEMM_SMEM3 (3 * BUF_W * 4)     // 49152 bytes

__device__ __forceinline__ int swz(int r, int w) {
    return r * 16 + (w ^ (((r >> 1) & 3) << 2));
}

__device__ __forceinline__ void stage_chunk3(
    const __half* __restrict__ Ah, const __half* __restrict__ Wh,
    const __half* __restrict__ Wm,
    uint32_t sbase, int buf, int k0, int tid)
{
    uint32_t s0 = sbase + buf * (BUF_W * 4);
#pragma unroll
    for (int i = 0; i < 8; i++) {
        int u = tid + i * 128;
        if (u < 512) {
            int r = u >> 2, ch = u & 3;
            cp_async16(s0 + (A_OFF_W + swz(r, ch * 4)) * 4,
                       Ah + r * D_MODEL + k0 + ch * 8);
        } else if (u < 768) {
            int u2 = u - 512;
            int r = u2 >> 2, ch = u2 & 3;
            cp_async16(s0 + (WH_OFF_W + swz(r, ch * 4)) * 4,
                       Wh + r * D_MODEL + k0 + ch * 8);
        } else {
            int u2 = u - 768;
            int r = u2 >> 2, ch = u2 & 3;
            cp_async16(s0 + (WM_OFF_W + swz(r, ch * 4)) * 4,
                       Wm + r * D_MODEL + k0 + ch * 8);
        }
    }
    cp_commit();
}

template <int MODE>
__device__ __forceinline__ void gemm_f16_body(
    const __half* __restrict__ Ah, const __half* __restrict__ Wh,
    const __half* __restrict__ Wm, const float* __restrict__ bias,
    float* __restrict__ C, __half* __restrict__ H,
    const float2* __restrict__ tab)
{
    extern __shared__ uint32_t smw[];
    const uint32_t sbase = smem_u32(smw);
    const int tid  = threadIdx.x;
    const int wid  = tid >> 5;
    const int lane = tid & 31;
    const int wm_  = (wid & 1) * 64;
    const int wn   = (wid >> 1) * 32;
    const int brow = blockIdx.y * 128;
    const int bcol = blockIdx.x * 64;
    const int g    = lane >> 2;
    const int t    = lane & 3;
    const int lrow16 = lane & 15;
    const int lrow8  = lane & 7;
    const int half_  = lane >> 4;
    const int midbit = (lane >> 3) & 1;

    uint32_t aoff[4][2], boff[2][2];
#pragma unroll
    for (int mf = 0; mf < 4; mf++)
#pragma unroll
        for (int ks = 0; ks < 2; ks++) {
            int row = wm_ + mf * 16 + lrow16;
            int ch  = ks * 2 + half_;
            aoff[mf][ks] = (uint32_t)((A_OFF_W + row * 16 +
                ((ch * 4) ^ (((row >> 1) & 3) << 2))) * 4);
        }
#pragma unroll
    for (int p = 0; p < 2; p++)
#pragma unroll
        for (int ks = 0; ks < 2; ks++) {
            int row = wn + (2 * p + half_) * 8 + lrow8;
            int ch  = ks * 2 + midbit;
            boff[p][ks] = (uint32_t)((row * 16 +
                ((ch * 4) ^ (((row >> 1) & 3) << 2))) * 4);
        }

    float acc[4][4][4];
#pragma unroll
    for (int mf = 0; mf < 4; mf++)
#pragma unroll
        for (int nf = 0; nf < 4; nf++)
#pragma unroll
            for (int r = 0; r < 4; r++) acc[mf][nf][r] = 0.0f;

    const __half* Ah_r = Ah + brow * D_MODEL;
    const __half* Wh_r = Wh + bcol * D_MODEL;
    const __half* Wm_r = Wm + bcol * D_MODEL;

    stage_chunk3(Ah_r, Wh_r, Wm_r, sbase, 0, 0, tid);
    stage_chunk3(Ah_r, Wh_r, Wm_r, sbase, 1, BK2, tid);

    int buf = 0;
    for (int c = 0; c < NCH2; c++) {
        if (c < NCH2 - 1) cp_wait<1>(); else cp_wait<0>();
        __syncthreads();
        if (c + 2 < NCH2) {
            int nb = buf + 2; if (nb >= 3) nb -= 3;
            stage_chunk3(Ah_r, Wh_r, Wm_r, sbase, nb, (c + 2) * BK2, tid);
        }

        const uint32_t sb0 = sbase + buf * (BUF_W * 4);

#pragma unroll
        for (int ks = 0; ks < 2; ks++) {
            uint32_t ah[4][4];
#pragma unroll
            for (int mf = 0; mf < 4; mf++)
                ldsm4(ah[mf], sb0 + aoff[mf][ks]);
#pragma unroll
            for (int p = 0; p < 2; p++) {
                uint32_t bh4[4], bm4[4];
                ldsm4(bh4, sb0 + WH_OFF_W * 4 + boff[p][ks]);
                ldsm4(bm4, sb0 + WM_OFF_W * 4 + boff[p][ks]);
#pragma unroll
                for (int qq = 0; qq < 2; qq++) {
                    const int nf = 2 * p + qq;
                    uint32_t bh[2] = { bh4[2 * qq], bh4[2 * qq + 1] };
                    uint32_t bm[2] = { bm4[2 * qq], bm4[2 * qq + 1] };
#pragma unroll
                    for (int mf = 0; mf < 4; mf++) {
                        mma_f16(acc[mf][nf], ah[mf], bm);
                        mma_f16(acc[mf][nf], ah[mf], bh);
                    }
                }
            }
        }
        buf++; if (buf >= 3) buf = 0;
    }

    if (MODE == 0) {
#pragma unroll
        for (int mf = 0; mf < 4; mf++) {
            int row0 = brow + wm_ + mf * 16 + g;
#pragma unroll
            for (int nf = 0; nf < 4; nf++) {
                int col = bcol + wn + nf * 8 + 2 * t;
                float b0 = bias[col], b1 = bias[col + 1];
                float2 v0 = make_float2(acc[mf][nf][0] + b0, acc[mf][nf][1] + b1);
                float2 v1 = make_float2(acc[mf][nf][2] + b0, acc[mf][nf][3] + b1);
                *(float2*)(C + row0 * D_MODEL + col)       = v0;
                *(float2*)(C + (row0 + 8) * D_MODEL + col) = v1;
            }
        }
        return;
    }

    // MODE 1/2: stage acc+bias to smem [128][66] fp32, then transform.
    float* smf = (float*)smw;
    __syncthreads();   // ring no longer needed; smem reads from mainloop done
#pragma unroll
    for (int mf = 0; mf < 4; mf++) {
        int row0 = wm_ + mf * 16 + g;
#pragma unroll
        for (int nf = 0; nf < 4; nf++) {
            int col = wn + nf * 8 + 2 * t;
            float b0 = bias[bcol + col], b1 = bias[bcol + col + 1];
            smf[row0 * 66 + col]           = acc[mf][nf][0] + b0;
            smf[row0 * 66 + col + 1]       = acc[mf][nf][1] + b1;
            smf[(row0 + 8) * 66 + col]     = acc[mf][nf][2] + b0;
            smf[(row0 + 8) * 66 + col + 1] = acc[mf][nf][3] + b1;
        }
    }
    __syncthreads();

    if (MODE == 1) {
        // RoPE + fp16: thread = one row; 8 groups of 4 freq pairs.
        int row  = tid;
        int grow = brow + row;
        int tpos = grow & (SEQ - 1);
        const float* sr = smf + row * 66;
        const float2* tp = tab + (tpos << 5);
        __half* Hr = H + grow * D_MODEL + bcol;
#pragma unroll
        for (int gi = 0; gi < 8; gi++) {
            int d0 = gi * 4;
            float ra[4], rb[4];
#pragma unroll
            for (int j = 0; j < 4; j++) {
                float a = sr[d0 + j];
                float b = sr[d0 + j + 32];
                float2 cs = tp[d0 + j];
                ra[j] = a * cs.x - b * cs.y;
                rb[j] = b * cs.x + a * cs.y;
            }
            *(uint2*)(Hr + d0)      = make_uint2(pack_f16(ra[0], ra[1]),
                                                 pack_f16(ra[2], ra[3]));
            *(uint2*)(Hr + d0 + 32) = make_uint2(pack_f16(rb[0], rb[1]),
                                                 pack_f16(rb[2], rb[3]));
        }
    } else {
        // V^T fp16: thread = (d, s-half); write 64 contiguous s values.
        int d  = tid >> 1;
        int sh = tid & 1;
        int b_ = brow >> 11;                       // batch (2048 rows each)
        int h_ = bcol >> 6;                        // head
        __half* Ho = H + (((b_ * 16 + h_) * 64 + d) * SEQ) +
                     (brow & (SEQ - 1)) + sh * 64;
#pragma unroll
        for (int j0 = 0; j0 < 64; j0 += 8) {
            __half tmp[8];
#pragma unroll
            for (int j = 0; j < 8; j++)
                tmp[j] = __float2half_rn(smf[(sh * 64 + j0 + j) * 66 + d]);
            *(uint4*)(Ho + j0) = *(uint4*)tmp;
        }
    }
}

__global__ __launch_bounds__(128, 4)
void gemm_qkv_f16(const __half* __restrict__ Xh,
                  const __half* __restrict__ Wqh, const __half* __restrict__ Wqm,
                  const float* __restrict__ Bq,
                  const __half* __restrict__ Wkh, const __half* __restrict__ Wkm,
                  const float* __restrict__ Bk,
                  const __half* __restrict__ Wvh, const __half* __restrict__ Wvm,
                  const float* __restrict__ Bv,
                  __half* __restrict__ Qh, __half* __restrict__ Kh,
                  __half* __restrict__ Vth, const float2* __restrict__ tab)
{
    if (blockIdx.z == 0)
        gemm_f16_body<1>(Xh, Wqh, Wqm, Bq, nullptr, Qh, tab);
    else if (blockIdx.z == 1)
        gemm_f16_body<1>(Xh, Wkh, Wkm, Bk, nullptr, Kh, tab);
    else
        gemm_f16_body<2>(Xh, Wvh, Wvm, Bv, nullptr, Vth, tab);
}

__global__ __launch_bounds__(128, 4)
void gemm_out_f16(const __half* __restrict__ Ah,
                  const __half* __restrict__ Wh, const __half* __restrict__ Wm,
                  const float* __restrict__ bb, float* __restrict__ C)
{
    gemm_f16_body<0>(Ah, Wh, Wm, bb, C, nullptr, nullptr);
}

// ---------------------------------------------------------------------------
// Flash attention, single-term fp16 (validated round 12).
// ---------------------------------------------------------------------------
#define NT        (SEQ / 64)
#define FL_QH     0
#define FL_STG    18432
#define FL_SSZ    18688
#define FL_KH(s)  (FL_STG + (s) * FL_SSZ)
#define FL_VH(s)  (FL_STG + (s) * FL_SSZ + 9216)
#define FL_MS(s)  (FL_STG + (s) * FL_SSZ + 18432)
#define FA4_SMEM  (FL_STG + 2 * FL_SSZ)   // 55808

__global__ __launch_bounds__(256)
void flash4_kernel(const __half* __restrict__ Qh,
                   const __half* __restrict__ Kh,
                   const __half* __restrict__ Vth,
                   const float* __restrict__ mask,
                   __half* __restrict__ Oh)
{
    extern __shared__ char sm2[];
    const int tid  = threadIdx.x;
    const int w    = tid >> 5;
    const int lane = tid & 31;
    const int g    = lane >> 2;
    const int t    = lane & 3;
    const int qt   = blockIdx.x;
    const int bh   = blockIdx.y;
    const int b    = bh >> 4;
    const int h    = bh & 15;
    const uint32_t sbase = smem_u32(sm2);
    const int lrow16 = lane & 15;
    const int lrow8  = lane & 7;
    const int half_  = lane >> 4;
    const int midbit = (lane >> 3) & 1;

    uint32_t qoff[4], koff[4][4];
#pragma unroll
    for (int ks = 0; ks < 4; ks++)
        qoff[ks] = (uint32_t)((w * 16 + lrow16) * 144 + (ks * 2 + half_) * 16);
#pragma unroll
    for (int p = 0; p < 4; p++)
#pragma unroll
        for (int ks = 0; ks < 4; ks++)
            koff[p][ks] = (uint32_t)(((2 * p + half_) * 8 + lrow8) * 144 +
                                     (ks * 2 + midbit) * 16);

    const __half* qh_g = Qh + (b * SEQ + qt * 128) * D_MODEL + h * HDIM;
    const __half* kh_g = Kh + b * SEQ * D_MODEL + h * HDIM;
    const __half* vh_g = Vth + bh * HDIM * SEQ;
    const float* mask_g = mask + b * SEQ;

    auto stage = [&](int kt, int s) {
#pragma unroll
        for (int i = 0; i < 2; i++) {
            int idx = tid + i * 256;
            int r   = idx >> 3;
            int ch  = idx & 7;
            cp_async16(sbase + FL_KH(s) + r * 144 + ch * 16,
                       kh_g + (kt * 64 + r) * D_MODEL + ch * 8);
            cp_async16(sbase + FL_VH(s) + r * 144 + ch * 16,
                       vh_g + r * SEQ + kt * 64 + ch * 8);
        }
        if (tid < 16)
            cp_async16(sbase + FL_MS(s) + tid * 16, mask_g + kt * 64 + tid * 4);
    };

#pragma unroll
    for (int i = 0; i < 2; i++) {
        int idx = tid + i * 256;
        int r   = idx >> 2;
        int ch  = (idx & 3) * 2;
        cp_async16(sbase + FL_QH + r * 144 + ch * 16, qh_g + r * D_MODEL + ch * 8);
        cp_async16(sbase + FL_QH + r * 144 + (ch + 1) * 16, qh_g + r * D_MODEL + (ch + 1) * 8);
    }
    stage(0, 0);
    cp_commit();

    float o[8][4];
#pragma unroll
    for (int nf = 0; nf < 8; nf++)
#pragma unroll
        for (int j = 0; j < 4; j++) o[nf][j] = 0.0f;
    float m0 = -1e30f, m1 = -1e30f, l0 = 0.0f, l1 = 0.0f;

    for (int kt = 0; kt < NT; kt++) {
        const int s = kt & 1;
        if (kt + 1 < NT) { stage(kt + 1, s ^ 1); cp_commit(); cp_wait<1>(); }
        else             { cp_wait<0>(); }
        __syncthreads();

        float sc[8][4];
#pragma unroll
        for (int nf = 0; nf < 8; nf++)
#pragma unroll
            for (int j = 0; j < 4; j++) sc[nf][j] = 0.0f;

#pragma unroll
        for (int ks = 0; ks < 4; ks++) {
            uint32_t ah[4];
            ldsm4(ah, sbase + FL_QH + qoff[ks]);
#pragma unroll
            for (int p = 0; p < 4; p++) {
                uint32_t bh4[4];
                ldsm4(bh4, sbase + FL_KH(s) + koff[p][ks]);
#pragma unroll
                for (int qq = 0; qq < 2; qq++) {
                    uint32_t bhf[2] = { bh4[2 * qq], bh4[2 * qq + 1] };
                    mma_f16(sc[2 * p + qq], ah, bhf);
                }
            }
        }

        float rmax0 = -1e30f, rmax1 = -1e30f;
#pragma unroll
        for (int nf = 0; nf < 8; nf++) {
            float2 mk = *(const float2*)(sm2 + FL_MS(s) + (nf * 8 + 2 * t) * 4);
            sc[nf][0] = fmaf(sc[nf][0], 0.125f, mk.x);
            sc[nf][1] = fmaf(sc[nf][1], 0.125f, mk.y);
            sc[nf][2] = fmaf(sc[nf][2], 0.125f, mk.x);
            sc[nf][3] = fmaf(sc[nf][3], 0.125f, mk.y);
            rmax0 = fmaxf(rmax0, fmaxf(sc[nf][0], sc[nf][1]));
            rmax1 = fmaxf(rmax1, fmaxf(sc[nf][2], sc[nf][3]));
        }
        rmax0 = fmaxf(rmax0, __shfl_xor_sync(0xffffffffu, rmax0, 1));
        rmax0 = fmaxf(rmax0, __shfl_xor_sync(0xffffffffu, rmax0, 2));
        rmax1 = fmaxf(rmax1, __shfl_xor_sync(0xffffffffu, rmax1, 1));
        rmax1 = fmaxf(rmax1, __shfl_xor_sync(0xffffffffu, rmax1, 2));
        float mn0 = fmaxf(m0, rmax0), mn1 = fmaxf(m1, rmax1);
        float c0 = fast_exp(m0 - mn0), c1 = fast_exp(m1 - mn1);
        float sum0 = 0.0f, sum1 = 0.0f;
#pragma unroll
        for (int nf = 0; nf < 8; nf++) {
            sc[nf][0] = fast_exp(sc[nf][0] - mn0);
            sc[nf][1] = fast_exp(sc[nf][1] - mn0);
            sc[nf][2] = fast_exp(sc[nf][2] - mn1);
            sc[nf][3] = fast_exp(sc[nf][3] - mn1);
            sum0 += sc[nf][0] + sc[nf][1];
            sum1 += sc[nf][2] + sc[nf][3];
        }
        sum0 += __shfl_xor_sync(0xffffffffu, sum0, 1);
        sum0 += __shfl_xor_sync(0xffffffffu, sum0, 2);
        sum1 += __shfl_xor_sync(0xffffffffu, sum1, 1);
        sum1 += __shfl_xor_sync(0xffffffffu, sum1, 2);
        l0 = l0 * c0 + sum0;
        l1 = l1 * c1 + sum1;
        m0 = mn0; m1 = mn1;
#pragma unroll
        for (int nf = 0; nf < 8; nf++) {
            o[nf][0] *= c0; o[nf][1] *= c0;
            o[nf][2] *= c1; o[nf][3] *= c1;
        }

#pragma unroll
        for (int ks = 0; ks < 4; ks++) {
            uint32_t ph[4];
            ph[0] = pack_f16(sc[2 * ks][0],     sc[2 * ks][1]);
            ph[1] = pack_f16(sc[2 * ks][2],     sc[2 * ks][3]);
            ph[2] = pack_f16(sc[2 * ks + 1][0], sc[2 * ks + 1][1]);
            ph[3] = pack_f16(sc[2 * ks + 1][2], sc[2 * ks + 1][3]);
#pragma unroll
            for (int p = 0; p < 4; p++) {
                uint32_t bh4[4];
                ldsm4(bh4, sbase + FL_VH(s) + koff[p][ks]);
#pragma unroll
                for (int qq = 0; qq < 2; qq++) {
                    uint32_t bhf[2] = { bh4[2 * qq], bh4[2 * qq + 1] };
                    mma_f16(o[2 * p + qq], ph, bhf);
                }
            }
        }
        __syncthreads();
    }

    float i0 = 1.0f / l0, i1 = 1.0f / l1;
    int row0 = b * SEQ + qt * 128 + w * 16 + g;
    int colb = h * HDIM + 2 * t;
#pragma unroll
    for (int nf = 0; nf < 8; nf++) {
        uint32_t hw0 = pack_f16(o[nf][0] * i0, o[nf][1] * i0);
        uint32_t hw1 = pack_f16(o[nf][2] * i1, o[nf][3] * i1);
        *(uint32_t*)(Oh + row0 * D_MODEL + colb + nf * 8)       = hw0;
        *(uint32_t*)(Oh + (row0 + 8) * D_MODEL + colb + nf * 8) = hw1;
    }
}

// ---------------------------------------------------------------------------
// Launch
// ---------------------------------------------------------------------------
extern "C" void kernel_launch(void* const* d_in, const int* in_sizes, int n_in,
                              void* d_out, int out_size)
{
    const float* x    = (const float*)d_in[0];
    const float* wq   = (const float*)d_in[1];
    const float* bq   = (const float*)d_in[2];
    const float* wk   = (const float*)d_in[3];
    const float* bk   = (const float*)d_in[4];
    const float* wv   = (const float*)d_in[5];
    const float* bv   = (const float*)d_in[6];
    const float* wo   = (const float*)d_in[7];
    const float* bo   = (const float*)d_in[8];
    const float* mask = (const float*)d_in[9];
    float* out = (float*)d_out;

    float2* angtab;
    __half *qh, *kh, *vth, *xh, *ath;
    __half *wqh, *wqm, *wkh, *wkm, *wvh, *wvm, *woh, *wom;
    cudaGetSymbolAddress((void**)&angtab, g_angtab);
    cudaGetSymbolAddress((void**)&qh,  g_qh);
    cudaGetSymbolAddress((void**)&kh,  g_kh);
    cudaGetSymbolAddress((void**)&vth, g_vth);
    cudaGetSymbolAddress((void**)&xh,  g_xh);
    cudaGetSymbolAddress((void**)&ath, g_ath);
    cudaGetSymbolAddress((void**)&wqh, g_wqh);
    cudaGetSymbolAddress((void**)&wqm, g_wqm);
    cudaGetSymbolAddress((void**)&wkh, g_wkh);
    cudaGetSymbolAddress((void**)&wkm, g_wkm);
    cudaGetSymbolAddress((void**)&wvh, g_wvh);
    cudaGetSymbolAddress((void**)&wvm, g_wvm);
    cudaGetSymbolAddress((void**)&woh, g_woh);
    cudaGetSymbolAddress((void**)&wom, g_wom);

    cudaFuncSetAttribute(gemm_qkv_f16,
                         cudaFuncAttributeMaxDynamicSharedMemorySize, GEMM_SMEM3);
    cudaFuncSetAttribute(gemm_out_f16,
                         cudaFuncAttributeMaxDynamicSharedMemorySize, GEMM_SMEM3);
    cudaFuncSetAttribute(flash4_kernel,
                         cudaFuncAttributeMaxDynamicSharedMemorySize, FA4_SMEM);

    // Prepasses
    const int NX4 = ROWS * D_MODEL / 4;
    angtab_kernel<<<SEQ * 32 / 256, 256>>>(angtab);
    split_w4_kernel<<<(4 * W_UNITS / 2) / 256, 256>>>(
        wq, wk, wv, wo, wqh, wqm, wkh, wkm, wvh, wvm, woh, wom);
    split1_kernel<<<(NX4 / 2) / 256, 256>>>(x, xh, NX4);

    // QKV projections with fused RoPE / V^T epilogues
    dim3 g1(D_MODEL / 64, ROWS / 128, 3);
    gemm_qkv_f16<<<g1, 128, GEMM_SMEM3>>>(xh, wqh, wqm, bq,
                                          wkh, wkm, bk, wvh, wvm, bv,
                                          qh, kh, vth, angtab);

    // Flash attention (single-term fp16)
    flash4_kernel<<<dim3(SEQ / 128, BATCH * N_HEADS), 256, FA4_SMEM>>>(
        qh, kh, vth, mask, ath);

    // Output projection (fp16x2) -> d_out
    dim3 g3(D_MODEL / 64, ROWS / 128);
    gemm_out_f16<<<g3, 128, GEMM_SMEM3>>>(ath, woh, wom, bo, out);
}

// round 16
// speedup vs baseline: 1.0894x; 1.0894x over previous
#include <cuda_runtime.h>
#include <cuda_fp16.h>
#include <cstdint>
#include <math.h>

#define D_MODEL 1024
#define N_HEADS 16
#define HDIM    64
#define SEQ     2048
#define BATCH   2
#define ROWS    (BATCH * SEQ)   // 4096

// ---------------------------------------------------------------------------
// Scratch (static device globals — no allocation allowed)
// ---------------------------------------------------------------------------
__device__ float g_q[ROWS * D_MODEL];
__device__ float g_k[ROWS * D_MODEL];
__device__ float g_v[ROWS * D_MODEL];
__device__ float2 g_angtab[SEQ * 32];                         // (cos, sin)
__device__ __half g_qh[ROWS * D_MODEL];                       // Q hi
__device__ __half g_kh[ROWS * D_MODEL];                       // K hi
__device__ __half g_vth[BATCH * N_HEADS * HDIM * SEQ];        // V^T hi [bh*64+d][s]
__device__ __half g_xh[ROWS * D_MODEL];                       // X hi
__device__ __half g_ath[ROWS * D_MODEL];                      // att hi
__device__ __half g_wqh[D_MODEL * D_MODEL];
__device__ __half g_wqm[D_MODEL * D_MODEL];
__device__ __half g_wkh[D_MODEL * D_MODEL];
__device__ __half g_wkm[D_MODEL * D_MODEL];
__device__ __half g_wvh[D_MODEL * D_MODEL];
__device__ __half g_wvm[D_MODEL * D_MODEL];
__device__ __half g_woh[D_MODEL * D_MODEL];
__device__ __half g_wom[D_MODEL * D_MODEL];

// ---------------------------------------------------------------------------
// Helpers
// ---------------------------------------------------------------------------
__device__ __forceinline__ uint32_t smem_u32(const void* p) {
    uint32_t a;
    asm("{ .reg .u64 t; cvta.to.shared.u64 t, %1; cvt.u32.u64 %0, t; }"
        : "=r"(a) : "l"(p));
    return a;
}
__device__ __forceinline__ void cp_async16(uint32_t saddr, const void* gptr) {
    asm volatile("cp.async.cg.shared.global [%0], [%1], 16;"
                 :: "r"(saddr), "l"(gptr) : "memory");
}
__device__ __forceinline__ void cp_commit() {
    asm volatile("cp.async.commit_group;" ::: "memory");
}
template <int N>
__device__ __forceinline__ void cp_wait() {
    asm volatile("cp.async.wait_group %0;" :: "n"(N) : "memory");
}
__device__ __forceinline__ void mma_f16(float* d, const uint32_t* a,
                                        const uint32_t* b) {
    asm volatile(
        "mma.sync.aligned.m16n8k16.row.col.f32.f16.f16.f32 "
        "{%0,%1,%2,%3}, {%4,%5,%6,%7}, {%8,%9}, {%0,%1,%2,%3};"
        : "+f"(d[0]), "+f"(d[1]), "+f"(d[2]), "+f"(d[3])
        : "r"(a[0]), "r"(a[1]), "r"(a[2]), "r"(a[3]), "r"(b[0]), "r"(b[1]));
}
__device__ __forceinline__ void ldsm4(uint32_t* r, uint32_t addr) {
    asm volatile("ldmatrix.sync.aligned.m8n8.x4.shared.b16 {%0,%1,%2,%3}, [%4];"
                 : "=r"(r[0]), "=r"(r[1]), "=r"(r[2]), "=r"(r[3]) : "r"(addr));
}
__device__ __forceinline__ uint32_t pack_f16(float lo, float hi) {
    uint32_t r;
    asm("cvt.rn.f16x2.f32 %0, %1, %2;" : "=r"(r) : "f"(hi), "f"(lo));
    return r;
}

// FFMA-only exp, accurate ~1e-7 on [-87, 0]
__device__ __forceinline__ float fast_exp(float x) {
    x = fmaxf(x, -87.0f);
    float y = x * 1.4426950408889634f;
    float r = y + 12582912.0f;
    float n = r - 12582912.0f;
    float f = y - n;
    float t = f * 0.6931471805599453f;
    float p = 1.3888889e-3f;
    p = fmaf(p, t, 8.3333333e-3f);
    p = fmaf(p, t, 4.1666667e-2f);
    p = fmaf(p, t, 1.6666667e-1f);
    p = fmaf(p, t, 0.5f);
    p = fmaf(p, t, 1.0f);
    p = fmaf(p, t, 1.0f);
    int ni = __float_as_int(r) - 0x4B400000;
    float scale = __int_as_float((ni << 23) + 0x3F800000);
    return p * scale;
}

// ---------------------------------------------------------------------------
// RoPE angle table
// ---------------------------------------------------------------------------
__global__ __launch_bounds__(256)
void angtab_kernel(float2* __restrict__ tab)
{
    int idx = blockIdx.x * blockDim.x + threadIdx.x;
    int t = idx >> 5;
    int i = idx & 31;
    float inv = 1.0f / powf(10000.0f, (float)(2 * i) * (1.0f / 64.0f));
    float ang = (float)t * inv;
    float sn, cs;
    sincosf(ang, &sn, &cs);
    tab[idx] = make_float2(cs, sn);
}

// ---------------------------------------------------------------------------
// Weight split (hi + mid), fused over the 4 matrices.
// ---------------------------------------------------------------------------
#define W_UNITS (D_MODEL * D_MODEL / 4)

__global__ __launch_bounds__(256)
void split_w4_kernel(const float* __restrict__ w0, const float* __restrict__ w1,
                     const float* __restrict__ w2, const float* __restrict__ w3,
                     __half* __restrict__ h0, __half* __restrict__ m0,
                     __half* __restrict__ h1, __half* __restrict__ m1,
                     __half* __restrict__ h2, __half* __restrict__ m2,
                     __half* __restrict__ h3, __half* __restrict__ m3)
{
    int idx = blockIdx.x * blockDim.x + threadIdx.x;
    int u   = idx * 2;
    int mat = u >> 18;
    int rem = u & (W_UNITS - 1);
    const float* src; __half *hh, *mm;
    if (mat == 0)      { src = w0; hh = h0; mm = m0; }
    else if (mat == 1) { src = w1; hh = h1; mm = m1; }
    else if (mat == 2) { src = w2; hh = h2; mm = m2; }
    else               { src = w3; hh = h3; mm = m3; }
#pragma unroll
    for (int j = 0; j < 2; j++) {
        int o = rem + j;
        float4 x = *(const float4*)(src + o * 4);
        __half ha = __float2half_rn(x.x);
        __half hb = __float2half_rn(x.y);
        __half hc = __float2half_rn(x.z);
        __half hd = __float2half_rn(x.w);
        __half2* hp = (__half2*)(hh + o * 4);
        hp[0] = __half2(ha, hb);
        hp[1] = __half2(hc, hd);
        __half2* mp = (__half2*)(mm + o * 4);
        mp[0] = __half2(__float2half_rn(x.x - __half2float(ha)),
                        __float2half_rn(x.y - __half2float(hb)));
        mp[1] = __half2(__float2half_rn(x.z - __half2float(hc)),
                        __float2half_rn(x.w - __half2float(hd)));
    }
}

// X split (hi only)
__global__ __launch_bounds__(256)
void split1_kernel(const float* __restrict__ src, __half* __restrict__ h, int n4)
{
    int idx = blockIdx.x * blockDim.x + threadIdx.x;
#pragma unroll
    for (int j = 0; j < 2; j++) {
        int o = idx * 2 + j;
        if (o >= n4) return;
        float4 x = *(const float4*)(src + o * 4);
        __half2* hp = (__half2*)(h + o * 4);
        hp[0] = __half2(__float2half_rn(x.x), __float2half_rn(x.y));
        hp[1] = __half2(__float2half_rn(x.z), __float2half_rn(x.w));
    }
}

// ---------------------------------------------------------------------------
// fp16x2 GEMM: C[M,N] = A[M,K] @ W[N,K]^T + bias; terms ah*wh + ah*wm.
// 128-thread CTA (4 warps as 2x2), CTA tile 128x64, warp tile 64x32.
// 3-stage cp.async ring, XOR swizzle, ldmatrix, 4 CTAs/SM. (Round-13 design.)
// ---------------------------------------------------------------------------
#define BK2      32
#define NCH2     (D_MODEL / BK2)       // 32 chunks
#define BUF_W    4096                  // words per stage (16KB)
#define A_OFF_W  0
#define WH_OFF_W 2048
#define WM_OFF_W 3072
#define GEMM_SMEM3 (3 * BUF_W * 4)     // 49152 bytes

__device__ __forceinline__ int swz(int r, int w) {
    return r * 16 + (w ^ (((r >> 1) & 3) << 2));
}

__device__ __forceinline__ void stage_chunk3(
    const __half* __restrict__ Ah, const __half* __restrict__ Wh,
    const __half* __restrict__ Wm,
    uint32_t sbase, int buf, int k0, int tid)
{
    uint32_t s0 = sbase + buf * (BUF_W * 4);
#pragma unroll
    for (int i = 0; i < 8; i++) {
        int u = tid + i * 128;
        if (u < 512) {
            int r = u >> 2, ch = u & 3;
            cp_async16(s0 + (A_OFF_W + swz(r, ch * 4)) * 4,
                       Ah + r * D_MODEL + k0 + ch * 8);
        } else if (u < 768) {
            int u2 = u - 512;
            int r = u2 >> 2, ch = u2 & 3;
            cp_async16(s0 + (WH_OFF_W + swz(r, ch * 4)) * 4,
                       Wh + r * D_MODEL + k0 + ch * 8);
        } else {
            int u2 = u - 768;
            int r = u2 >> 2, ch = u2 & 3;
            cp_async16(s0 + (WM_OFF_W + swz(r, ch * 4)) * 4,
                       Wm + r * D_MODEL + k0 + ch * 8);
        }
    }
    cp_commit();
}

__device__ __forceinline__ void gemm_f16_body(
    const __half* __restrict__ Ah, const __half* __restrict__ Wh,
    const __half* __restrict__ Wm,
    const float* __restrict__ bias, float* __restrict__ C)
{
    extern __shared__ uint32_t smw[];
    const uint32_t sbase = smem_u32(smw);
    const int tid  = threadIdx.x;
    const int wid  = tid >> 5;
    const int lane = tid & 31;
    const int wm_  = (wid & 1) * 64;
    const int wn   = (wid >> 1) * 32;
    const int brow = blockIdx.y * 128;
    const int bcol = blockIdx.x * 64;
    const int g    = lane >> 2;
    const int t    = lane & 3;
    const int lrow16 = lane & 15;
    const int lrow8  = lane & 7;
    const int half_  = lane >> 4;
    const int midbit = (lane >> 3) & 1;

    uint32_t aoff[4][2], boff[2][2];
#pragma unroll
    for (int mf = 0; mf < 4; mf++)
#pragma unroll
        for (int ks = 0; ks < 2; ks++) {
            int row = wm_ + mf * 16 + lrow16;
            int ch  = ks * 2 + half_;
            aoff[mf][ks] = (uint32_t)((A_OFF_W + row * 16 +
                ((ch * 4) ^ (((row >> 1) & 3) << 2))) * 4);
        }
#pragma unroll
    for (int p = 0; p < 2; p++)
#pragma unroll
        for (int ks = 0; ks < 2; ks++) {
            int row = wn + (2 * p + half_) * 8 + lrow8;
            int ch  = ks * 2 + midbit;
            boff[p][ks] = (uint32_t)((row * 16 +
                ((ch * 4) ^ (((row >> 1) & 3) << 2))) * 4);
        }

    float acc[4][4][4];
#pragma unroll
    for (int mf = 0; mf < 4; mf++)
#pragma unroll
        for (int nf = 0; nf < 4; nf++)
#pragma unroll
            for (int r = 0; r < 4; r++) acc[mf][nf][r] = 0.0f;

    const __half* Ah_r = Ah + brow * D_MODEL;
    const __half* Wh_r = Wh + bcol * D_MODEL;
    const __half* Wm_r = Wm + bcol * D_MODEL;

    stage_chunk3(Ah_r, Wh_r, Wm_r, sbase, 0, 0, tid);
    stage_chunk3(Ah_r, Wh_r, Wm_r, sbase, 1, BK2, tid);

    int buf = 0;
    for (int c = 0; c < NCH2; c++) {
        if (c < NCH2 - 1) cp_wait<1>(); else cp_wait<0>();
        __syncthreads();
        if (c + 2 < NCH2) {
            int nb = buf + 2; if (nb >= 3) nb -= 3;
            stage_chunk3(Ah_r, Wh_r, Wm_r, sbase, nb, (c + 2) * BK2, tid);
        }

        const uint32_t sb0 = sbase + buf * (BUF_W * 4);

#pragma unroll
        for (int ks = 0; ks < 2; ks++) {
            uint32_t ah[4][4];
#pragma unroll
            for (int mf = 0; mf < 4; mf++)
                ldsm4(ah[mf], sb0 + aoff[mf][ks]);
#pragma unroll
            for (int p = 0; p < 2; p++) {
                uint32_t bh4[4], bm4[4];
                ldsm4(bh4, sb0 + WH_OFF_W * 4 + boff[p][ks]);
                ldsm4(bm4, sb0 + WM_OFF_W * 4 + boff[p][ks]);
#pragma unroll
                for (int qq = 0; qq < 2; qq++) {
                    const int nf = 2 * p + qq;
                    uint32_t bh[2] = { bh4[2 * qq], bh4[2 * qq + 1] };
                    uint32_t bm[2] = { bm4[2 * qq], bm4[2 * qq + 1] };
#pragma unroll
                    for (int mf = 0; mf < 4; mf++) {
                        mma_f16(acc[mf][nf], ah[mf], bm);
                        mma_f16(acc[mf][nf], ah[mf], bh);
                    }
                }
            }
        }
        buf++; if (buf >= 3) buf = 0;
    }

#pragma unroll
    for (int mf = 0; mf < 4; mf++) {
        int row0 = brow + wm_ + mf * 16 + g;
#pragma unroll
        for (int nf = 0; nf < 4; nf++) {
            int col = bcol + wn + nf * 8 + 2 * t;
            float b0 = bias[col], b1 = bias[col + 1];
            float2 v0 = make_float2(acc[mf][nf][0] + b0, acc[mf][nf][1] + b1);
            float2 v1 = make_float2(acc[mf][nf][2] + b0, acc[mf][nf][3] + b1);
            *(float2*)(C + row0 * D_MODEL + col)       = v0;
            *(float2*)(C + (row0 + 8) * D_MODEL + col) = v1;
        }
    }
}

__global__ __launch_bounds__(128, 4)
void gemm_qkv_f16(const __half* __restrict__ Xh,
                  const __half* __restrict__ Wqh, const __half* __restrict__ Wqm,
                  const float* __restrict__ Bq, float* __restrict__ Oq,
                  const __half* __restrict__ Wkh, const __half* __restrict__ Wkm,
                  const float* __restrict__ Bk, float* __restrict__ Ok,
                  const __half* __restrict__ Wvh, const __half* __restrict__ Wvm,
                  const float* __restrict__ Bv, float* __restrict__ Ov)
{
    const __half *Wh, *Wm; const float* bb; float* C;
    if (blockIdx.z == 0)      { Wh = Wqh; Wm = Wqm; bb = Bq; C = Oq; }
    else if (blockIdx.z == 1) { Wh = Wkh; Wm = Wkm; bb = Bk; C = Ok; }
    else                      { Wh = Wvh; Wm = Wvm; bb = Bv; C = Ov; }
    gemm_f16_body(Xh, Wh, Wm, bb, C);
}

__global__ __launch_bounds__(128, 4)
void gemm_out_f16(const __half* __restrict__ Ah,
                  const __half* __restrict__ Wh, const __half* __restrict__ Wm,
                  const float* __restrict__ bb, float* __restrict__ C)
{
    gemm_f16_body(Ah, Wh, Wm, bb, C);
}

// ---------------------------------------------------------------------------
// RoPE + split, table-based: q,k -> fp16 hi only.
// ---------------------------------------------------------------------------
__global__ __launch_bounds__(256)
void rope_split_kernel(const float* __restrict__ q, const float* __restrict__ k,
                       const float2* __restrict__ tab,
                       __half* __restrict__ qh, __half* __restrict__ kh)
{
    int idx = blockIdx.x * blockDim.x + threadIdx.x;
    int i4  = idx & 7;
    int h   = (idx >> 3) & (N_HEADS - 1);
    int row = idx >> 7;
    int t   = row & (SEQ - 1);

    int base = row * D_MODEL + h * HDIM + i4 * 4;
    float4 qa = *(const float4*)(q + base);
    float4 qb = *(const float4*)(q + base + 32);
    float4 ka = *(const float4*)(k + base);
    float4 kb = *(const float4*)(k + base + 32);
    const float2* tp = tab + (t << 5) + i4 * 4;

    float qa_[4] = { qa.x, qa.y, qa.z, qa.w };
    float qb_[4] = { qb.x, qb.y, qb.z, qb.w };
    float ka_[4] = { ka.x, ka.y, ka.z, ka.w };
    float kb_[4] = { kb.x, kb.y, kb.z, kb.w };
    float qr_a[4], qr_b[4], kr_a[4], kr_b[4];
#pragma unroll
    for (int j = 0; j < 4; j++) {
        float2 cs = tp[j];
        qr_a[j] = qa_[j] * cs.x - qb_[j] * cs.y;
        qr_b[j] = qb_[j] * cs.x + qa_[j] * cs.y;
        kr_a[j] = ka_[j] * cs.x - kb_[j] * cs.y;
        kr_b[j] = kb_[j] * cs.x + ka_[j] * cs.y;
    }

    *(uint2*)(qh + base)      = make_uint2(pack_f16(qr_a[0], qr_a[1]),
                                           pack_f16(qr_a[2], qr_a[3]));
    *(uint2*)(qh + base + 32) = make_uint2(pack_f16(qr_b[0], qr_b[1]),
                                           pack_f16(qr_b[2], qr_b[3]));
    *(uint2*)(kh + base)      = make_uint2(pack_f16(kr_a[0], kr_a[1]),
                                           pack_f16(kr_a[2], kr_a[3]));
    *(uint2*)(kh + base + 32) = make_uint2(pack_f16(kr_b[0], kr_b[1]),
                                           pack_f16(kr_b[2], kr_b[3]));
}

// ---------------------------------------------------------------------------
// V transpose to fp16 hi
// ---------------------------------------------------------------------------
__global__ __launch_bounds__(256)
void v_split_t_kernel(const float* __restrict__ v, __half* __restrict__ vth)
{
    __shared__ __half th[64][66];
    const int tid = threadIdx.x;
    const int st  = blockIdx.x;
    const int bh  = blockIdx.y;
    const int b   = bh >> 4;
    const int h   = bh & 15;
    const int s0  = st * 64;

#pragma unroll
    for (int l = 0; l < 16; l++) {
        int e = l * 256 + tid;
        int r = e >> 6, d = e & 63;
        th[d][r] = __float2half_rn(v[(b * SEQ + s0 + r) * D_MODEL + h * HDIM + d]);
    }
    __syncthreads();
#pragma unroll
    for (int l = 0; l < 16; l++) {
        int e = l * 256 + tid;
        int d = e >> 6, sc = e & 63;
        vth[(bh * HDIM + d) * SEQ + s0 + sc] = th[d][sc];
    }
}

// ---------------------------------------------------------------------------
// Flash attention, single-term fp16, 128-thread CTAs (64 q-rows, 4 warps),
// 4 CTAs/SM -> 4 barrier domains. Warp-local softmax unchanged.
// ---------------------------------------------------------------------------
#define NT        (SEQ / 64)
#define FL_QH     0
#define FL_STG    9216      // Q: 64 rows x 144B
#define FL_SSZ    18688     // KH 9216 + VH 9216 + mask 256
#define FL_KH(s)  (FL_STG + (s) * FL_SSZ)
#define FL_VH(s)  (FL_STG + (s) * FL_SSZ + 9216)
#define FL_MS(s)  (FL_STG + (s) * FL_SSZ + 18432)
#define FA4_SMEM  (FL_STG + 2 * FL_SSZ)   // 46592

__global__ __launch_bounds__(128, 4)
void flash4_kernel(const __half* __restrict__ Qh,
                   const __half* __restrict__ Kh,
                   const __half* __restrict__ Vth,
                   const float* __restrict__ mask,
                   __half* __restrict__ Oh)
{
    extern __shared__ char sm2[];
    const int tid  = threadIdx.x;
    const int w    = tid >> 5;           // 0..3
    const int lane = tid & 31;
    const int g    = lane >> 2;
    const int t    = lane & 3;
    const int qt   = blockIdx.x;         // 64-row q tile
    const int bh   = blockIdx.y;
    const int b    = bh >> 4;
    const int h    = bh & 15;
    const uint32_t sbase = smem_u32(sm2);
    const int lrow16 = lane & 15;
    const int lrow8  = lane & 7;
    const int half_  = lane >> 4;
    const int midbit = (lane >> 3) & 1;

    uint32_t qoff[4], koff[4][4];
#pragma unroll
    for (int ks = 0; ks < 4; ks++)
        qoff[ks] = (uint32_t)((w * 16 + lrow16) * 144 + (ks * 2 + half_) * 16);
#pragma unroll
    for (int p = 0; p < 4; p++)
#pragma unroll
        for (int ks = 0; ks < 4; ks++)
            koff[p][ks] = (uint32_t)(((2 * p + half_) * 8 + lrow8) * 144 +
                                     (ks * 2 + midbit) * 16);

    const __half* qh_g = Qh + (b * SEQ + qt * 64) * D_MODEL + h * HDIM;
    const __half* kh_g = Kh + b * SEQ * D_MODEL + h * HDIM;
    const __half* vh_g = Vth + bh * HDIM * SEQ;
    const float* mask_g = mask + b * SEQ;

    auto stage = [&](int kt, int s) {
#pragma unroll
        for (int i = 0; i < 4; i++) {
            int idx = tid + i * 128;           // 0..511
            int r   = idx >> 3;                // 0..63
            int ch  = idx & 7;
            cp_async16(sbase + FL_KH(s) + r * 144 + ch * 16,
                       kh_g + (kt * 64 + r) * D_MODEL + ch * 8);
            cp_async16(sbase + FL_VH(s) + r * 144 + ch * 16,
                       vh_g + r * SEQ + kt * 64 + ch * 8);
        }
        if (tid < 16)
            cp_async16(sbase + FL_MS(s) + tid * 16, mask_g + kt * 64 + tid * 4);
    };

    // Q tile: 64 rows x 8 chunks = 512 units
#pragma unroll
    for (int i = 0; i < 4; i++) {
        int idx = tid + i * 128;
        int r   = idx >> 3;
        int ch  = idx & 7;
        cp_async16(sbase + FL_QH + r * 144 + ch * 16, qh_g + r * D_MODEL + ch * 8);
    }
    stage(0, 0);
    cp_commit();

    float o[8][4];
#pragma unroll
    for (int nf = 0; nf < 8; nf++)
#pragma unroll
        for (int j = 0; j < 4; j++) o[nf][j] = 0.0f;
    float m0 = -1e30f, m1 = -1e30f, l0 = 0.0f, l1 = 0.0f;

    for (int kt = 0; kt < NT; kt++) {
        const int s = kt & 1;
        if (kt + 1 < NT) { stage(kt + 1, s ^ 1); cp_commit(); cp_wait<1>(); }
        else             { cp_wait<0>(); }
        __syncthreads();

        float sc[8][4];
#pragma unroll
        for (int nf = 0; nf < 8; nf++)
#pragma unroll
            for (int j = 0; j < 4; j++) sc[nf][j] = 0.0f;

#pragma unroll
        for (int ks = 0; ks < 4; ks++) {
            uint32_t ah[4];
            ldsm4(ah, sbase + FL_QH + qoff[ks]);
#pragma unroll
            for (int p = 0; p < 4; p++) {
                uint32_t bh4[4];
                ldsm4(bh4, sbase + FL_KH(s) + koff[p][ks]);
#pragma unroll
                for (int qq = 0; qq < 2; qq++) {
                    uint32_t bhf[2] = { bh4[2 * qq], bh4[2 * qq + 1] };
                    mma_f16(sc[2 * p + qq], ah, bhf);
                }
            }
        }

        float rmax0 = -1e30f, rmax1 = -1e30f;
#pragma unroll
        for (int nf = 0; nf < 8; nf++) {
            float2 mk = *(const float2*)(sm2 + FL_MS(s) + (nf * 8 + 2 * t) * 4);
            sc[nf][0] = fmaf(sc[nf][0], 0.125f, mk.x);
            sc[nf][1] = fmaf(sc[nf][1], 0.125f, mk.y);
            sc[nf][2] = fmaf(sc[nf][2], 0.125f, mk.x);
            sc[nf][3] = fmaf(sc[nf][3], 0.125f, mk.y);
            rmax0 = fmaxf(rmax0, fmaxf(sc[nf][0], sc[nf][1]));
            rmax1 = fmaxf(rmax1, fmaxf(sc[nf][2], sc[nf][3]));
        }
        rmax0 = fmaxf(rmax0, __shfl_xor_sync(0xffffffffu, rmax0, 1));
        rmax0 = fmaxf(rmax0, __shfl_xor_sync(0xffffffffu, rmax0, 2));
        rmax1 = fmaxf(rmax1, __shfl_xor_sync(0xffffffffu, rmax1, 1));
        rmax1 = fmaxf(rmax1, __shfl_xor_sync(0xffffffffu, rmax1, 2));
        float mn0 = fmaxf(m0, rmax0), mn1 = fmaxf(m1, rmax1);
        float c0 = fast_exp(m0 - mn0), c1 = fast_exp(m1 - mn1);
        float sum0 = 0.0f, sum1 = 0.0f;
#pragma unroll
        for (int nf = 0; nf < 8; nf++) {
            sc[nf][0] = fast_exp(sc[nf][0] - mn0);
            sc[nf][1] = fast_exp(sc[nf][1] - mn0);
            sc[nf][2] = fast_exp(sc[nf][2] - mn1);
            sc[nf][3] = fast_exp(sc[nf][3] - mn1);
            sum0 += sc[nf][0] + sc[nf][1];
            sum1 += sc[nf][2] + sc[nf][3];
        }
        sum0 += __shfl_xor_sync(0xffffffffu, sum0, 1);
        sum0 += __shfl_xor_sync(0xffffffffu, sum0, 2);
        sum1 += __shfl_xor_sync(0xffffffffu, sum1, 1);
        sum1 += __shfl_xor_sync(0xffffffffu, sum1, 2);
        l0 = l0 * c0 + sum0;
        l1 = l1 * c1 + sum1;
        m0 = mn0; m1 = mn1;
#pragma unroll
        for (int nf = 0; nf < 8; nf++) {
            o[nf][0] *= c0; o[nf][1] *= c0;
            o[nf][2] *= c1; o[nf][3] *= c1;
        }

#pragma unroll
        for (int ks = 0; ks < 4; ks++) {
            uint32_t ph[4];
            ph[0] = pack_f16(sc[2 * ks][0],     sc[2 * ks][1]);
            ph[1] = pack_f16(sc[2 * ks][2],     sc[2 * ks][3]);
            ph[2] = pack_f16(sc[2 * ks + 1][0], sc[2 * ks + 1][1]);
            ph[3] = pack_f16(sc[2 * ks + 1][2], sc[2 * ks + 1][3]);
#pragma unroll
            for (int p = 0; p < 4; p++) {
                uint32_t bh4[4];
                ldsm4(bh4, sbase + FL_VH(s) + koff[p][ks]);
#pragma unroll
                for (int qq = 0; qq < 2; qq++) {
                    uint32_t bhf[2] = { bh4[2 * qq], bh4[2 * qq + 1] };
                    mma_f16(o[2 * p + qq], ph, bhf);
                }
            }
        }
        __syncthreads();
    }

    float i0 = 1.0f / l0, i1 = 1.0f / l1;
    int row0 = b * SEQ + qt * 64 + w * 16 + g;
    int colb = h * HDIM + 2 * t;
#pragma unroll
    for (int nf = 0; nf < 8; nf++) {
        uint32_t hw0 = pack_f16(o[nf][0] * i0, o[nf][1] * i0);
        uint32_t hw1 = pack_f16(o[nf][2] * i1, o[nf][3] * i1);
        *(uint32_t*)(Oh + row0 * D_MODEL + colb + nf * 8)       = hw0;
        *(uint32_t*)(Oh + (row0 + 8) * D_MODEL + colb + nf * 8) = hw1;
    }
}

// ---------------------------------------------------------------------------
// Launch
// ---------------------------------------------------------------------------
extern "C" void kernel_launch(void* const* d_in, const int* in_sizes, int n_in,
                              void* d_out, int out_size)
{
    const float* x    = (const float*)d_in[0];
    const float* wq   = (const float*)d_in[1];
    const float* bq   = (const float*)d_in[2];
    const float* wk   = (const float*)d_in[3];
    const float* bk   = (const float*)d_in[4];
    const float* wv   = (const float*)d_in[5];
    const float* bv   = (const float*)d_in[6];
    const float* wo   = (const float*)d_in[7];
    const float* bo   = (const float*)d_in[8];
    const float* mask = (const float*)d_in[9];
    float* out = (float*)d_out;

    float *q, *k, *v;
    float2* angtab;
    __half *qh, *kh, *vth, *xh, *ath;
    __half *wqh, *wqm, *wkh, *wkm, *wvh, *wvm, *woh, *wom;
    cudaGetSymbolAddress((void**)&q,      g_q);
    cudaGetSymbolAddress((void**)&k,      g_k);
    cudaGetSymbolAddress((void**)&v,      g_v);
    cudaGetSymbolAddress((void**)&angtab, g_angtab);
    cudaGetSymbolAddress((void**)&qh,  g_qh);
    cudaGetSymbolAddress((void**)&kh,  g_kh);
    cudaGetSymbolAddress((void**)&vth, g_vth);
    cudaGetSymbolAddress((void**)&xh,  g_xh);
    cudaGetSymbolAddress((void**)&ath, g_ath);
    cudaGetSymbolAddress((void**)&wqh, g_wqh);
    cudaGetSymbolAddress((void**)&wqm, g_wqm);
    cudaGetSymbolAddress((void**)&wkh, g_wkh);
    cudaGetSymbolAddress((void**)&wkm, g_wkm);
    cudaGetSymbolAddress((void**)&wvh, g_wvh);
    cudaGetSymbolAddress((void**)&wvm, g_wvm);
    cudaGetSymbolAddress((void**)&woh, g_woh);
    cudaGetSymbolAddress((void**)&wom, g_wom);

    cudaFuncSetAttribute(gemm_qkv_f16,
                         cudaFuncAttributeMaxDynamicSharedMemorySize, GEMM_SMEM3);
    cudaFuncSetAttribute(gemm_out_f16,
                         cudaFuncAttributeMaxDynamicSharedMemorySize, GEMM_SMEM3);
    cudaFuncSetAttribute(flash4_kernel,
                         cudaFuncAttributeMaxDynamicSharedMemorySize, FA4_SMEM);

    // Prepasses
    const int NX4 = ROWS * D_MODEL / 4;
    angtab_kernel<<<SEQ * 32 / 256, 256>>>(angtab);
    split_w4_kernel<<<(4 * W_UNITS / 2) / 256, 256>>>(
        wq, wk, wv, wo, wqh, wqm, wkh, wkm, wvh, wvm, woh, wom);
    split1_kernel<<<(NX4 / 2) / 256, 256>>>(x, xh, NX4);

    // QKV projections (fp16x2 mma.sync, 128-thread CTAs, 4/SM)
    dim3 g1(D_MODEL / 64, ROWS / 128, 3);
    gemm_qkv_f16<<<g1, 128, GEMM_SMEM3>>>(xh, wqh, wqm, bq, q,
                                          wkh, wkm, bk, k, wvh, wvm, bv, v);

    // RoPE (table) + fp16 hi split
    int rope_items = ROWS * N_HEADS * 8;
    rope_split_kernel<<<rope_items / 256, 256>>>(q, k, angtab, qh, kh);

    // V transpose (hi only)
    v_split_t_kernel<<<dim3(SEQ / 64, BATCH * N_HEADS), 256>>>(v, vth);

    // Flash attention (single-term fp16, 128-thread CTAs, 4/SM)
    flash4_kernel<<<dim3(SEQ / 64, BATCH * N_HEADS), 128, FA4_SMEM>>>(
        qh, kh, vth, mask, ath);

    // Output projection (fp16x2) -> d_out
    dim3 g3(D_MODEL / 64, ROWS / 128);
    gemm_out_f16<<<g3, 128, GEMM_SMEM3>>>(ath, woh, wom, bo, out);
}

// round 17
// speedup vs baseline: 1.3740x; 1.2612x over previous
#include <cuda_runtime.h>
#include <cuda_fp16.h>
#include <cstdint>
#include <math.h>

#define D_MODEL 1024
#define N_HEADS 16
#define HDIM    64
#define SEQ     2048
#define BATCH   2
#define ROWS    (BATCH * SEQ)   // 4096

// ---------------------------------------------------------------------------
// Scratch (static device globals — no allocation allowed)
// ---------------------------------------------------------------------------
__device__ float g_q[ROWS * D_MODEL];
__device__ float g_k[ROWS * D_MODEL];
__device__ float g_v[ROWS * D_MODEL];
__device__ float2 g_angtab[SEQ * 32];                         // (cos, sin)
__device__ __half g_qh[ROWS * D_MODEL];                       // Q hi
__device__ __half g_kh[ROWS * D_MODEL];                       // K hi
__device__ __half g_vth[BATCH * N_HEADS * HDIM * SEQ];        // V^T hi [bh*64+d][s]
__device__ __half g_xh[ROWS * D_MODEL];                       // X hi
__device__ __half g_ath[ROWS * D_MODEL];                      // att hi
__device__ __half g_wqh[D_MODEL * D_MODEL];
__device__ __half g_wkh[D_MODEL * D_MODEL];
__device__ __half g_wvh[D_MODEL * D_MODEL];
__device__ __half g_woh[D_MODEL * D_MODEL];

// ---------------------------------------------------------------------------
// Helpers
// ---------------------------------------------------------------------------
__device__ __forceinline__ uint32_t smem_u32(const void* p) {
    uint32_t a;
    asm("{ .reg .u64 t; cvta.to.shared.u64 t, %1; cvt.u32.u64 %0, t; }"
        : "=r"(a) : "l"(p));
    return a;
}
__device__ __forceinline__ void cp_async16(uint32_t saddr, const void* gptr) {
    asm volatile("cp.async.cg.shared.global [%0], [%1], 16;"
                 :: "r"(saddr), "l"(gptr) : "memory");
}
__device__ __forceinline__ void cp_commit() {
    asm volatile("cp.async.commit_group;" ::: "memory");
}
template <int N>
__device__ __forceinline__ void cp_wait() {
    asm volatile("cp.async.wait_group %0;" :: "n"(N) : "memory");
}
__device__ __forceinline__ void mma_f16(float* d, const uint32_t* a,
                                        const uint32_t* b) {
    asm volatile(
        "mma.sync.aligned.m16n8k16.row.col.f32.f16.f16.f32 "
        "{%0,%1,%2,%3}, {%4,%5,%6,%7}, {%8,%9}, {%0,%1,%2,%3};"
        : "+f"(d[0]), "+f"(d[1]), "+f"(d[2]), "+f"(d[3])
        : "r"(a[0]), "r"(a[1]), "r"(a[2]), "r"(a[3]), "r"(b[0]), "r"(b[1]));
}
__device__ __forceinline__ void ldsm4(uint32_t* r, uint32_t addr) {
    asm volatile("ldmatrix.sync.aligned.m8n8.x4.shared.b16 {%0,%1,%2,%3}, [%4];"
                 : "=r"(r[0]), "=r"(r[1]), "=r"(r[2]), "=r"(r[3]) : "r"(addr));
}
__device__ __forceinline__ uint32_t pack_f16(float lo, float hi) {
    uint32_t r;
    asm("cvt.rn.f16x2.f32 %0, %1, %2;" : "=r"(r) : "f"(hi), "f"(lo));
    return r;
}

// FFMA-only exp, accurate ~1e-7 on [-87, 0]
__device__ __forceinline__ float fast_exp(float x) {
    x = fmaxf(x, -87.0f);
    float y = x * 1.4426950408889634f;
    float r = y + 12582912.0f;
    float n = r - 12582912.0f;
    float f = y - n;
    float t = f * 0.6931471805599453f;
    float p = 1.3888889e-3f;
    p = fmaf(p, t, 8.3333333e-3f);
    p = fmaf(p, t, 4.1666667e-2f);
    p = fmaf(p, t, 1.6666667e-1f);
    p = fmaf(p, t, 0.5f);
    p = fmaf(p, t, 1.0f);
    p = fmaf(p, t, 1.0f);
    int ni = __float_as_int(r) - 0x4B400000;
    float scale = __int_as_float((ni << 23) + 0x3F800000);
    return p * scale;
}

// ---------------------------------------------------------------------------
// RoPE angle table
// ---------------------------------------------------------------------------
__global__ __launch_bounds__(256)
void angtab_kernel(float2* __restrict__ tab)
{
    int idx = blockIdx.x * blockDim.x + threadIdx.x;
    int t = idx >> 5;
    int i = idx & 31;
    float inv = 1.0f / powf(10000.0f, (float)(2 * i) * (1.0f / 64.0f));
    float ang = (float)t * inv;
    float sn, cs;
    sincosf(ang, &sn, &cs);
    tab[idx] = make_float2(cs, sn);
}

// ---------------------------------------------------------------------------
// Weight split (hi only), fused over the 4 matrices.
// ---------------------------------------------------------------------------
#define W_UNITS (D_MODEL * D_MODEL / 4)

__global__ __launch_bounds__(256)
void split_w4_kernel(const float* __restrict__ w0, const float* __restrict__ w1,
                     const float* __restrict__ w2, const float* __restrict__ w3,
                     __half* __restrict__ h0, __half* __restrict__ h1,
                     __half* __restrict__ h2, __half* __restrict__ h3)
{
    int idx = blockIdx.x * blockDim.x + threadIdx.x;
    int u   = idx * 2;
    int mat = u >> 18;
    int rem = u & (W_UNITS - 1);
    const float* src; __half* hh;
    if (mat == 0)      { src = w0; hh = h0; }
    else if (mat == 1) { src = w1; hh = h1; }
    else if (mat == 2) { src = w2; hh = h2; }
    else               { src = w3; hh = h3; }
#pragma unroll
    for (int j = 0; j < 2; j++) {
        int o = rem + j;
        float4 x = *(const float4*)(src + o * 4);
        __half2* hp = (__half2*)(hh + o * 4);
        hp[0] = __half2(__float2half_rn(x.x), __float2half_rn(x.y));
        hp[1] = __half2(__float2half_rn(x.z), __float2half_rn(x.w));
    }
}

// X split (hi only)
__global__ __launch_bounds__(256)
void split1_kernel(const float* __restrict__ src, __half* __restrict__ h, int n4)
{
    int idx = blockIdx.x * blockDim.x + threadIdx.x;
#pragma unroll
    for (int j = 0; j < 2; j++) {
        int o = idx * 2 + j;
        if (o >= n4) return;
        float4 x = *(const float4*)(src + o * 4);
        __half2* hp = (__half2*)(h + o * 4);
        hp[0] = __half2(__float2half_rn(x.x), __float2half_rn(x.y));
        hp[1] = __half2(__float2half_rn(x.z), __float2half_rn(x.w));
    }
}

// ---------------------------------------------------------------------------
// Single-term fp16 GEMM: C[M,N] = Ah[M,K] @ Wh[N,K]^T + bias (fp32 accum).
// 128-thread CTA (4 warps as 2x2), CTA tile 128x64, warp tile 64x32.
// 3-stage cp.async ring (12KB/stage: A 8KB + Wh 4KB), XOR swizzle, ldmatrix,
// 4 CTAs/SM.
// ---------------------------------------------------------------------------
#define BK2      32
#define NCH2     (D_MODEL / BK2)       // 32 chunks
#define BUF_W    3072                  // words per stage (12KB)
#define A_OFF_W  0                     // A: 128 rows x 16 words
#define WH_OFF_W 2048                  // Wh: 64 rows x 16 words
#define GEMM_SMEM3 (3 * BUF_W * 4)     // 36864 bytes

__device__ __forceinline__ int swz(int r, int w) {
    return r * 16 + (w ^ (((r >> 1) & 3) << 2));
}

__device__ __forceinline__ void stage_chunk3(
    const __half* __restrict__ Ah, const __half* __restrict__ Wh,
    uint32_t sbase, int buf, int k0, int tid)
{
    uint32_t s0 = sbase + buf * (BUF_W * 4);
#pragma unroll
    for (int i = 0; i < 6; i++) {
        int u = tid + i * 128;            // 0..767 16B-units
        if (u < 512) {                    // A: 128 rows x 4 units
            int r = u >> 2, ch = u & 3;
            cp_async16(s0 + (A_OFF_W + swz(r, ch * 4)) * 4,
                       Ah + r * D_MODEL + k0 + ch * 8);
        } else {                          // Wh: 64 rows x 4 units
            int u2 = u - 512;
            int r = u2 >> 2, ch = u2 & 3;
            cp_async16(s0 + (WH_OFF_W + swz(r, ch * 4)) * 4,
                       Wh + r * D_MODEL + k0 + ch * 8);
        }
    }
    cp_commit();
}

__device__ __forceinline__ void gemm_f16_body(
    const __half* __restrict__ Ah, const __half* __restrict__ Wh,
    const float* __restrict__ bias, float* __restrict__ C)
{
    extern __shared__ uint32_t smw[];
    const uint32_t sbase = smem_u32(smw);
    const int tid  = threadIdx.x;
    const int wid  = tid >> 5;
    const int lane = tid & 31;
    const int wm_  = (wid & 1) * 64;
    const int wn   = (wid >> 1) * 32;
    const int brow = blockIdx.y * 128;
    const int bcol = blockIdx.x * 64;
    const int g    = lane >> 2;
    const int t    = lane & 3;
    const int lrow16 = lane & 15;
    const int lrow8  = lane & 7;
    const int half_  = lane >> 4;
    const int midbit = (lane >> 3) & 1;

    uint32_t aoff[4][2], boff[2][2];
#pragma unroll
    for (int mf = 0; mf < 4; mf++)
#pragma unroll
        for (int ks = 0; ks < 2; ks++) {
            int row = wm_ + mf * 16 + lrow16;
            int ch  = ks * 2 + half_;
            aoff[mf][ks] = (uint32_t)((A_OFF_W + row * 16 +
                ((ch * 4) ^ (((row >> 1) & 3) << 2))) * 4);
        }
#pragma unroll
    for (int p = 0; p < 2; p++)
#pragma unroll
        for (int ks = 0; ks < 2; ks++) {
            int row = wn + (2 * p + half_) * 8 + lrow8;
            int ch  = ks * 2 + midbit;
            boff[p][ks] = (uint32_t)((WH_OFF_W + row * 16 +
                ((ch * 4) ^ (((row >> 1) & 3) << 2))) * 4);
        }

    float acc[4][4][4];
#pragma unroll
    for (int mf = 0; mf < 4; mf++)
#pragma unroll
        for (int nf = 0; nf < 4; nf++)
#pragma unroll
            for (int r = 0; r < 4; r++) acc[mf][nf][r] = 0.0f;

    const __half* Ah_r = Ah + brow * D_MODEL;
    const __half* Wh_r = Wh + bcol * D_MODEL;

    stage_chunk3(Ah_r, Wh_r, sbase, 0, 0, tid);
    stage_chunk3(Ah_r, Wh_r, sbase, 1, BK2, tid);

    int buf = 0;
    for (int c = 0; c < NCH2; c++) {
        if (c < NCH2 - 1) cp_wait<1>(); else cp_wait<0>();
        __syncthreads();
        if (c + 2 < NCH2) {
            int nb = buf + 2; if (nb >= 3) nb -= 3;
            stage_chunk3(Ah_r, Wh_r, sbase, nb, (c + 2) * BK2, tid);
        }

        const uint32_t sb0 = sbase + buf * (BUF_W * 4);

#pragma unroll
        for (int ks = 0; ks < 2; ks++) {
            uint32_t ah[4][4];
#pragma unroll
            for (int mf = 0; mf < 4; mf++)
                ldsm4(ah[mf], sb0 + aoff[mf][ks]);
#pragma unroll
            for (int p = 0; p < 2; p++) {
                uint32_t bh4[4];
                ldsm4(bh4, sb0 + boff[p][ks]);
#pragma unroll
                for (int qq = 0; qq < 2; qq++) {
                    const int nf = 2 * p + qq;
                    uint32_t bh[2] = { bh4[2 * qq], bh4[2 * qq + 1] };
#pragma unroll
                    for (int mf = 0; mf < 4; mf++)
                        mma_f16(acc[mf][nf], ah[mf], bh);
                }
            }
        }
        buf++; if (buf >= 3) buf = 0;
    }

#pragma unroll
    for (int mf = 0; mf < 4; mf++) {
        int row0 = brow + wm_ + mf * 16 + g;
#pragma unroll
        for (int nf = 0; nf < 4; nf++) {
            int col = bcol + wn + nf * 8 + 2 * t;
            float b0 = bias[col], b1 = bias[col + 1];
            float2 v0 = make_float2(acc[mf][nf][0] + b0, acc[mf][nf][1] + b1);
            float2 v1 = make_float2(acc[mf][nf][2] + b0, acc[mf][nf][3] + b1);
            *(float2*)(C + row0 * D_MODEL + col)       = v0;
            *(float2*)(C + (row0 + 8) * D_MODEL + col) = v1;
        }
    }
}

__global__ __launch_bounds__(128, 4)
void gemm_qkv_f16(const __half* __restrict__ Xh,
                  const __half* __restrict__ Wqh, const float* __restrict__ Bq,
                  float* __restrict__ Oq,
                  const __half* __restrict__ Wkh, const float* __restrict__ Bk,
                  float* __restrict__ Ok,
                  const __half* __restrict__ Wvh, const float* __restrict__ Bv,
                  float* __restrict__ Ov)
{
    const __half* Wh; const float* bb; float* C;
    if (blockIdx.z == 0)      { Wh = Wqh; bb = Bq; C = Oq; }
    else if (blockIdx.z == 1) { Wh = Wkh; bb = Bk; C = Ok; }
    else                      { Wh = Wvh; bb = Bv; C = Ov; }
    gemm_f16_body(Xh, Wh, bb, C);
}

__global__ __launch_bounds__(128, 4)
void gemm_out_f16(const __half* __restrict__ Ah, const __half* __restrict__ Wh,
                  const float* __restrict__ bb, float* __restrict__ C)
{
    gemm_f16_body(Ah, Wh, bb, C);
}

// ---------------------------------------------------------------------------
// RoPE + split, table-based: q,k -> fp16 hi only.
// ---------------------------------------------------------------------------
__global__ __launch_bounds__(256)
void rope_split_kernel(const float* __restrict__ q, const float* __restrict__ k,
                       const float2* __restrict__ tab,
                       __half* __restrict__ qh, __half* __restrict__ kh)
{
    int idx = blockIdx.x * blockDim.x + threadIdx.x;
    int i4  = idx & 7;
    int h   = (idx >> 3) & (N_HEADS - 1);
    int row = idx >> 7;
    int t   = row & (SEQ - 1);

    int base = row * D_MODEL + h * HDIM + i4 * 4;
    float4 qa = *(const float4*)(q + base);
    float4 qb = *(const float4*)(q + base + 32);
    float4 ka = *(const float4*)(k + base);
    float4 kb = *(const float4*)(k + base + 32);
    const float2* tp = tab + (t << 5) + i4 * 4;

    float qa_[4] = { qa.x, qa.y, qa.z, qa.w };
    float qb_[4] = { qb.x, qb.y, qb.z, qb.w };
    float ka_[4] = { ka.x, ka.y, ka.z, ka.w };
    float kb_[4] = { kb.x, kb.y, kb.z, kb.w };
    float qr_a[4], qr_b[4], kr_a[4], kr_b[4];
#pragma unroll
    for (int j = 0; j < 4; j++) {
        float2 cs = tp[j];
        qr_a[j] = qa_[j] * cs.x - qb_[j] * cs.y;
        qr_b[j] = qb_[j] * cs.x + qa_[j] * cs.y;
        kr_a[j] = ka_[j] * cs.x - kb_[j] * cs.y;
        kr_b[j] = kb_[j] * cs.x + ka_[j] * cs.y;
    }

    *(uint2*)(qh + base)      = make_uint2(pack_f16(qr_a[0], qr_a[1]),
                                           pack_f16(qr_a[2], qr_a[3]));
    *(uint2*)(qh + base + 32) = make_uint2(pack_f16(qr_b[0], qr_b[1]),
                                           pack_f16(qr_b[2], qr_b[3]));
    *(uint2*)(kh + base)      = make_uint2(pack_f16(kr_a[0], kr_a[1]),
                                           pack_f16(kr_a[2], kr_a[3]));
    *(uint2*)(kh + base + 32) = make_uint2(pack_f16(kr_b[0], kr_b[1]),
                                           pack_f16(kr_b[2], kr_b[3]));
}

// ---------------------------------------------------------------------------
// V transpose to fp16 hi
// ---------------------------------------------------------------------------
__global__ __launch_bounds__(256)
void v_split_t_kernel(const float* __restrict__ v, __half* __restrict__ vth)
{
    __shared__ __half th[64][66];
    const int tid = threadIdx.x;
    const int st  = blockIdx.x;
    const int bh  = blockIdx.y;
    const int b   = bh >> 4;
    const int h   = bh & 15;
    const int s0  = st * 64;

#pragma unroll
    for (int l = 0; l < 16; l++) {
        int e = l * 256 + tid;
        int r = e >> 6, d = e & 63;
        th[d][r] = __float2half_rn(v[(b * SEQ + s0 + r) * D_MODEL + h * HDIM + d]);
    }
    __syncthreads();
#pragma unroll
    for (int l = 0; l < 16; l++) {
        int e = l * 256 + tid;
        int d = e >> 6, sc = e & 63;
        vth[(bh * HDIM + d) * SEQ + s0 + sc] = th[d][sc];
    }
}

// ---------------------------------------------------------------------------
// Flash attention, single-term fp16, 128-thread CTAs (64 q-rows, 4 warps),
// 4 CTAs/SM. (Validated round 16.)
// ---------------------------------------------------------------------------
#define NT        (SEQ / 64)
#define FL_QH     0
#define FL_STG    9216      // Q: 64 rows x 144B
#define FL_SSZ    18688     // KH 9216 + VH 9216 + mask 256
#define FL_KH(s)  (FL_STG + (s) * FL_SSZ)
#define FL_VH(s)  (FL_STG + (s) * FL_SSZ + 9216)
#define FL_MS(s)  (FL_STG + (s) * FL_SSZ + 18432)
#define FA4_SMEM  (FL_STG + 2 * FL_SSZ)   // 46592

__global__ __launch_bounds__(128, 4)
void flash4_kernel(const __half* __restrict__ Qh,
                   const __half* __restrict__ Kh,
                   const __half* __restrict__ Vth,
                   const float* __restrict__ mask,
                   __half* __restrict__ Oh)
{
    extern __shared__ char sm2[];
    const int tid  = threadIdx.x;
    const int w    = tid >> 5;
    const int lane = tid & 31;
    const int g    = lane >> 2;
    const int t    = lane & 3;
    const int qt   = blockIdx.x;
    const int bh   = blockIdx.y;
    const int b    = bh >> 4;
    const int h    = bh & 15;
    const uint32_t sbase = smem_u32(sm2);
    const int lrow16 = lane & 15;
    const int lrow8  = lane & 7;
    const int half_  = lane >> 4;
    const int midbit = (lane >> 3) & 1;

    uint32_t qoff[4], koff[4][4];
#pragma unroll
    for (int ks = 0; ks < 4; ks++)
        qoff[ks] = (uint32_t)((w * 16 + lrow16) * 144 + (ks * 2 + half_) * 16);
#pragma unroll
    for (int p = 0; p < 4; p++)
#pragma unroll
        for (int ks = 0; ks < 4; ks++)
            koff[p][ks] = (uint32_t)(((2 * p + half_) * 8 + lrow8) * 144 +
                                     (ks * 2 + midbit) * 16);

    const __half* qh_g = Qh + (b * SEQ + qt * 64) * D_MODEL + h * HDIM;
    const __half* kh_g = Kh + b * SEQ * D_MODEL + h * HDIM;
    const __half* vh_g = Vth + bh * HDIM * SEQ;
    const float* mask_g = mask + b * SEQ;

    auto stage = [&](int kt, int s) {
#pragma unroll
        for (int i = 0; i < 4; i++) {
            int idx = tid + i * 128;
            int r   = idx >> 3;
            int ch  = idx & 7;
            cp_async16(sbase + FL_KH(s) + r * 144 + ch * 16,
                       kh_g + (kt * 64 + r) * D_MODEL + ch * 8);
            cp_async16(sbase + FL_VH(s) + r * 144 + ch * 16,
                       vh_g + r * SEQ + kt * 64 + ch * 8);
        }
        if (tid < 16)
            cp_async16(sbase + FL_MS(s) + tid * 16, mask_g + kt * 64 + tid * 4);
    };

#pragma unroll
    for (int i = 0; i < 4; i++) {
        int idx = tid + i * 128;
        int r   = idx >> 3;
        int ch  = idx & 7;
        cp_async16(sbase + FL_QH + r * 144 + ch * 16, qh_g + r * D_MODEL + ch * 8);
    }
    stage(0, 0);
    cp_commit();

    float o[8][4];
#pragma unroll
    for (int nf = 0; nf < 8; nf++)
#pragma unroll
        for (int j = 0; j < 4; j++) o[nf][j] = 0.0f;
    float m0 = -1e30f, m1 = -1e30f, l0 = 0.0f, l1 = 0.0f;

    for (int kt = 0; kt < NT; kt++) {
        const int s = kt & 1;
        if (kt + 1 < NT) { stage(kt + 1, s ^ 1); cp_commit(); cp_wait<1>(); }
        else             { cp_wait<0>(); }
        __syncthreads();

        float sc[8][4];
#pragma unroll
        for (int nf = 0; nf < 8; nf++)
#pragma unroll
            for (int j = 0; j < 4; j++) sc[nf][j] = 0.0f;

#pragma unroll
        for (int ks = 0; ks < 4; ks++) {
            uint32_t ah[4];
            ldsm4(ah, sbase + FL_QH + qoff[ks]);
#pragma unroll
            for (int p = 0; p < 4; p++) {
                uint32_t bh4[4];
                ldsm4(bh4, sbase + FL_KH(s) + koff[p][ks]);
#pragma unroll
                for (int qq = 0; qq < 2; qq++) {
                    uint32_t bhf[2] = { bh4[2 * qq], bh4[2 * qq + 1] };
                    mma_f16(sc[2 * p + qq], ah, bhf);
                }
            }
        }

        float rmax0 = -1e30f, rmax1 = -1e30f;
#pragma unroll
        for (int nf = 0; nf < 8; nf++) {
            float2 mk = *(const float2*)(sm2 + FL_MS(s) + (nf * 8 + 2 * t) * 4);
            sc[nf][0] = fmaf(sc[nf][0], 0.125f, mk.x);
            sc[nf][1] = fmaf(sc[nf][1], 0.125f, mk.y);
            sc[nf][2] = fmaf(sc[nf][2], 0.125f, mk.x);
            sc[nf][3] = fmaf(sc[nf][3], 0.125f, mk.y);
            rmax0 = fmaxf(rmax0, fmaxf(sc[nf][0], sc[nf][1]));
            rmax1 = fmaxf(rmax1, fmaxf(sc[nf][2], sc[nf][3]));
        }
        rmax0 = fmaxf(rmax0, __shfl_xor_sync(0xffffffffu, rmax0, 1));
        rmax0 = fmaxf(rmax0, __shfl_xor_sync(0xffffffffu, rmax0, 2));
        rmax1 = fmaxf(rmax1, __shfl_xor_sync(0xffffffffu, rmax1, 1));
        rmax1 = fmaxf(rmax1, __shfl_xor_sync(0xffffffffu, rmax1, 2));
        float mn0 = fmaxf(m0, rmax0), mn1 = fmaxf(m1, rmax1);
        float c0 = fast_exp(m0 - mn0), c1 = fast_exp(m1 - mn1);
        float sum0 = 0.0f, sum1 = 0.0f;
#pragma unroll
        for (int nf = 0; nf < 8; nf++) {
            sc[nf][0] = fast_exp(sc[nf][0] - mn0);
            sc[nf][1] = fast_exp(sc[nf][1] - mn0);
            sc[nf][2] = fast_exp(sc[nf][2] - mn1);
            sc[nf][3] = fast_exp(sc[nf][3] - mn1);
            sum0 += sc[nf][0] + sc[nf][1];
            sum1 += sc[nf][2] + sc[nf][3];
        }
        sum0 += __shfl_xor_sync(0xffffffffu, sum0, 1);
        sum0 += __shfl_xor_sync(0xffffffffu, sum0, 2);
        sum1 += __shfl_xor_sync(0xffffffffu, sum1, 1);
        sum1 += __shfl_xor_sync(0xffffffffu, sum1, 2);
        l0 = l0 * c0 + sum0;
        l1 = l1 * c1 + sum1;
        m0 = mn0; m1 = mn1;
#pragma unroll
        for (int nf = 0; nf < 8; nf++) {
            o[nf][0] *= c0; o[nf][1] *= c0;
            o[nf][2] *= c1; o[nf][3] *= c1;
        }

#pragma unroll
        for (int ks = 0; ks < 4; ks++) {
            uint32_t ph[4];
            ph[0] = pack_f16(sc[2 * ks][0],     sc[2 * ks][1]);
            ph[1] = pack_f16(sc[2 * ks][2],     sc[2 * ks][3]);
            ph[2] = pack_f16(sc[2 * ks + 1][0], sc[2 * ks + 1][1]);
            ph[3] = pack_f16(sc[2 * ks + 1][2], sc[2 * ks + 1][3]);
#pragma unroll
            for (int p = 0; p < 4; p++) {
                uint32_t bh4[4];
                ldsm4(bh4, sbase + FL_VH(s) + koff[p][ks]);
#pragma unroll
                for (int qq = 0; qq < 2; qq++) {
                    uint32_t bhf[2] = { bh4[2 * qq], bh4[2 * qq + 1] };
                    mma_f16(o[2 * p + qq], ph, bhf);
                }
            }
        }
        __syncthreads();
    }

    float i0 = 1.0f / l0, i1 = 1.0f / l1;
    int row0 = b * SEQ + qt * 64 + w * 16 + g;
    int colb = h * HDIM + 2 * t;
#pragma unroll
    for (int nf = 0; nf < 8; nf++) {
        uint32_t hw0 = pack_f16(o[nf][0] * i0, o[nf][1] * i0);
        uint32_t hw1 = pack_f16(o[nf][2] * i1, o[nf][3] * i1);
        *(uint32_t*)(Oh + row0 * D_MODEL + colb + nf * 8)       = hw0;
        *(uint32_t*)(Oh + (row0 + 8) * D_MODEL + colb + nf * 8) = hw1;
    }
}

// ---------------------------------------------------------------------------
// Launch
// ---------------------------------------------------------------------------
extern "C" void kernel_launch(void* const* d_in, const int* in_sizes, int n_in,
                              void* d_out, int out_size)
{
    const float* x    = (const float*)d_in[0];
    const float* wq   = (const float*)d_in[1];
    const float* bq   = (const float*)d_in[2];
    const float* wk   = (const float*)d_in[3];
    const float* bk   = (const float*)d_in[4];
    const float* wv   = (const float*)d_in[5];
    const float* bv   = (const float*)d_in[6];
    const float* wo   = (const float*)d_in[7];
    const float* bo   = (const float*)d_in[8];
    const float* mask = (const float*)d_in[9];
    float* out = (float*)d_out;

    float *q, *k, *v;
    float2* angtab;
    __half *qh, *kh, *vth, *xh, *ath;
    __half *wqh, *wkh, *wvh, *woh;
    cudaGetSymbolAddress((void**)&q,      g_q);
    cudaGetSymbolAddress((void**)&k,      g_k);
    cudaGetSymbolAddress((void**)&v,      g_v);
    cudaGetSymbolAddress((void**)&angtab, g_angtab);
    cudaGetSymbolAddress((void**)&qh,  g_qh);
    cudaGetSymbolAddress((void**)&kh,  g_kh);
    cudaGetSymbolAddress((void**)&vth, g_vth);
    cudaGetSymbolAddress((void**)&xh,  g_xh);
    cudaGetSymbolAddress((void**)&ath, g_ath);
    cudaGetSymbolAddress((void**)&wqh, g_wqh);
    cudaGetSymbolAddress((void**)&wkh, g_wkh);
    cudaGetSymbolAddress((void**)&wvh, g_wvh);
    cudaGetSymbolAddress((void**)&woh, g_woh);

    cudaFuncSetAttribute(gemm_qkv_f16,
                         cudaFuncAttributeMaxDynamicSharedMemorySize, GEMM_SMEM3);
    cudaFuncSetAttribute(gemm_out_f16,
                         cudaFuncAttributeMaxDynamicSharedMemorySize, GEMM_SMEM3);
    cudaFuncSetAttribute(flash4_kernel,
                         cudaFuncAttributeMaxDynamicSharedMemorySize, FA4_SMEM);

    // Prepasses
    const int NX4 = ROWS * D_MODEL / 4;
    angtab_kernel<<<SEQ * 32 / 256, 256>>>(angtab);
    split_w4_kernel<<<(4 * W_UNITS / 2) / 256, 256>>>(
        wq, wk, wv, wo, wqh, wkh, wvh, woh);
    split1_kernel<<<(NX4 / 2) / 256, 256>>>(x, xh, NX4);

    // QKV projections (single-term fp16, 128-thread CTAs, 4/SM)
    dim3 g1(D_MODEL / 64, ROWS / 128, 3);
    gemm_qkv_f16<<<g1, 128, GEMM_SMEM3>>>(xh, wqh, bq, q,
                                          wkh, bk, k, wvh, bv, v);

    // RoPE (table) + fp16 hi split
    int rope_items = ROWS * N_HEADS * 8;
    rope_split_kernel<<<rope_items / 256, 256>>>(q, k, angtab, qh, kh);

    // V transpose (hi only)
    v_split_t_kernel<<<dim3(SEQ / 64, BATCH * N_HEADS), 256>>>(v, vth);

    // Flash attention (single-term fp16, 128-thread CTAs, 4/SM)
    flash4_kernel<<<dim3(SEQ / 64, BATCH * N_HEADS), 128, FA4_SMEM>>>(
        qh, kh, vth, mask, ath);

    // Output projection (single-term fp16) -> d_out
    dim3 g3(D_MODEL / 64, ROWS / 128);
    gemm_out_f16<<<g3, 128, GEMM_SMEM3>>>(ath, woh, bo, out);
}